// round 12
// baseline (speedup 1.0000x reference)
#include <cuda_runtime.h>
#include <math_constants.h>

#define HID   64
#define MAXN  50000

// Per-node precomputed tables, stride 8 floats for float4 alignment.
// srcTab[n*8 + 0..3] = ps (x0·Wsp + bsp), [n*8+4] = gs (x·Wsg + bsg)
// dstTab[n*8 + 0..3] = pd (x0·Wdp),       [n*8+4] = gd (x·Wdg + bdg)
__device__ float g_srcTab[MAXN * 8];
__device__ float g_dstTab[MAXN * 8];

// 8 lanes per node; lane handles elements [sub*4 .. sub*4+3] and [32+sub*4 ..].
// Butterfly transpose-reduce; distributed stores. Also zeroes output accumulators.
__global__ void node_kernel(const float* __restrict__ x,
                            const float* __restrict__ x0,
                            const float* __restrict__ Wsg, const float* __restrict__ bsg,
                            const float* __restrict__ Wdg, const float* __restrict__ bdg,
                            const float* __restrict__ Wsp, const float* __restrict__ bsp,
                            const float* __restrict__ Wdp,
                            float* __restrict__ atom, float* __restrict__ out0,
                            int n)
{
    int t    = blockIdx.x * blockDim.x + threadIdx.x;
    int node = t >> 3;
    int sub  = t & 7;
    if (node >= n) return;

    const size_t base = (size_t)node * HID;
    const int h0 = sub * 4;        // first element of chunk A
    const int h1 = 32 + sub * 4;   // first element of chunk B

    float4 xa  = *(const float4*)(x  + base + h0);
    float4 xb  = *(const float4*)(x  + base + h1);
    float4 x0a = *(const float4*)(x0 + base + h0);
    float4 x0b = *(const float4*)(x0 + base + h1);

    float gs = 0.f, gd = 0.f;
    float v[8];                    // 0..3 = ps partials, 4..7 = pd partials
#pragma unroll
    for (int p = 0; p < 8; p++) v[p] = 0.f;

    const float* xav  = (const float*)&xa;
    const float* xbv  = (const float*)&xb;
    const float* x0av = (const float*)&x0a;
    const float* x0bv = (const float*)&x0b;

#pragma unroll
    for (int k = 0; k < 4; k++) {
        int ha = h0 + k, hb = h1 + k;
        gs += xav[k] * __ldg(Wsg + ha) + xbv[k] * __ldg(Wsg + hb);
        gd += xav[k] * __ldg(Wdg + ha) + xbv[k] * __ldg(Wdg + hb);
        float4 wsa = *(const float4*)(Wsp + ha * 4);
        float4 wsb = *(const float4*)(Wsp + hb * 4);
        float4 wda = *(const float4*)(Wdp + ha * 4);
        float4 wdb = *(const float4*)(Wdp + hb * 4);
        v[0] += x0av[k] * wsa.x + x0bv[k] * wsb.x;
        v[1] += x0av[k] * wsa.y + x0bv[k] * wsb.y;
        v[2] += x0av[k] * wsa.z + x0bv[k] * wsb.z;
        v[3] += x0av[k] * wsa.w + x0bv[k] * wsb.w;
        v[4] += x0av[k] * wda.x + x0bv[k] * wdb.x;
        v[5] += x0av[k] * wda.y + x0bv[k] * wdb.y;
        v[6] += x0av[k] * wda.z + x0bv[k] * wdb.z;
        v[7] += x0av[k] * wda.w + x0bv[k] * wdb.w;
    }

    // transpose-reduce: 7 shuffles; lane sub ends with sum over group of v[sub]
    bool hi4 = (sub & 4) != 0;
    float a0k = hi4 ? v[4] : v[0], a0s = hi4 ? v[0] : v[4];
    float a1k = hi4 ? v[5] : v[1], a1s = hi4 ? v[1] : v[5];
    float a2k = hi4 ? v[6] : v[2], a2s = hi4 ? v[2] : v[6];
    float a3k = hi4 ? v[7] : v[3], a3s = hi4 ? v[3] : v[7];
    a0k += __shfl_xor_sync(0xffffffffu, a0s, 4);
    a1k += __shfl_xor_sync(0xffffffffu, a1s, 4);
    a2k += __shfl_xor_sync(0xffffffffu, a2s, 4);
    a3k += __shfl_xor_sync(0xffffffffu, a3s, 4);
    bool hi2 = (sub & 2) != 0;
    float b0k = hi2 ? a2k : a0k, b0s = hi2 ? a0k : a2k;
    float b1k = hi2 ? a3k : a1k, b1s = hi2 ? a1k : a3k;
    b0k += __shfl_xor_sync(0xffffffffu, b0s, 2);
    b1k += __shfl_xor_sync(0xffffffffu, b1s, 2);
    bool hi1 = (sub & 1) != 0;
    float ck = hi1 ? b1k : b0k, cs = hi1 ? b0k : b1k;
    ck += __shfl_xor_sync(0xffffffffu, cs, 1);

    // plain reduce for the two gate scalars (6 shuffles)
#pragma unroll
    for (int off = 4; off >= 1; off >>= 1) {
        gs += __shfl_xor_sync(0xffffffffu, gs, off);
        gd += __shfl_xor_sync(0xffffffffu, gd, off);
    }

    // distributed stores: lane sub<4 -> srcTab param, sub>=4 -> dstTab param
    if (sub < 4)
        g_srcTab[(size_t)node * 8 + sub] = ck + __ldg(bsp + sub);
    else
        g_dstTab[(size_t)node * 8 + (sub - 4)] = ck;
    if (sub == 0) {
        g_srcTab[(size_t)node * 8 + 4] = gs + __ldg(bsg);
        g_dstTab[(size_t)node * 8 + 4] = gd + __ldg(bdg);
        atom[node] = 0.0f;                 // zero the scatter accumulator
        if (node == 0) *out0 = 0.0f;       // zero the energy accumulator
    }
}

// Persistent grid-stride edge kernel — R8 body + cross-iteration index prefetch.
// Chunks of 256 edges (32 groups x 8). Pipelines across iterations:
//   - bond lengths for chunk i+1 loaded during iteration i (as in R8)
//   - src/dst indices for this lane's chunk-(i+1) tail edge ALSO loaded during
//     iteration i, so the tail's table gathers issue immediately with resolved
//     indices — one serial L2 trip on the tail chain instead of two.
__global__ void __launch_bounds__(256, 5)
edge_kernel(const float* __restrict__ y,
            const float* __restrict__ bondlength,
            const int* __restrict__ src,
            const int* __restrict__ dst,
            const float* __restrict__ Weg,
            const float* __restrict__ beg,
            float* __restrict__ atom,
            float* __restrict__ out0,
            int E, float invN)
{
    __shared__ float sWeg[HID];
    __shared__ float sEsum;
    int tid = threadIdx.x;
    if (tid < HID) sWeg[tid] = Weg[tid];
    if (tid == 0)  sEsum = 0.0f;
    __syncthreads();

    const int sub      = tid & 7;
    const int grpInBlk = tid >> 3;             // 0..31
    const float4 wa = *(const float4*)(sWeg + sub * 4);
    const float4 wb = *(const float4*)(sWeg + 32 + sub * 4);
    const float begv = __ldg(beg);

    const int CHUNK = 256;                     // edges per block-iteration
    const int nChunks = (E + CHUNK - 1) / CHUNK;

    float Vacc = 0.0f;
    int chunk = blockIdx.x;

    float r[8];
    int s_ = 0, dn = 0;                        // tail indices for CURRENT chunk
    if (chunk < nChunks) {
        int e0 = chunk * CHUNK + grpInBlk * 8;
#pragma unroll
        for (int p = 0; p < 8; p++)
            r[p] = (e0 + p < E) ? __ldg(bondlength + e0 + p) : 5.0f;
        int e = e0 + sub;
        if (e < E) { s_ = src[e]; dn = dst[e]; }
    }

    for (; chunk < nChunks; chunk += gridDim.x) {
        const int e0 = chunk * CHUNK + grpInBlk * 8;
        const float* ybase = y + (size_t)e0 * HID;

        // 1) y loads gated on already-resident r[] (evict-first stream)
        float d[8];
#pragma unroll
        for (int p = 0; p < 8; p += 2) {
            float da = 0.f, db = 0.f;
            if (r[p] <= 4.0f) {
                const float* row = ybase + (size_t)p * HID;
                float4 a = __ldcs((const float4*)(row + sub * 4));
                float4 b = __ldcs((const float4*)(row + 32 + sub * 4));
                da = a.x*wa.x + a.y*wa.y + a.z*wa.z + a.w*wa.w
                   + b.x*wb.x + b.y*wb.y + b.z*wb.z + b.w*wb.w;
            }
            if (r[p + 1] <= 4.0f) {
                const float* row = ybase + (size_t)(p + 1) * HID;
                float4 a = __ldcs((const float4*)(row + sub * 4));
                float4 b = __ldcs((const float4*)(row + 32 + sub * 4));
                db = a.x*wa.x + a.y*wa.y + a.z*wa.z + a.w*wa.w
                   + b.x*wb.x + b.y*wb.y + b.z*wb.z + b.w*wb.w;
            }
            d[p] = da; d[p + 1] = db;
        }

        // 2) prefetch NEXT chunk's bond lengths and tail indices
        int ns = 0, ndn = 0;
        {
            int nchunk = chunk + gridDim.x;
            if (nchunk < nChunks) {
                int ne0 = nchunk * CHUNK + grpInBlk * 8;
#pragma unroll
                for (int p = 0; p < 8; p++)
                    r[p] = (ne0 + p < E) ? __ldg(bondlength + ne0 + p) : 5.0f;
                int ne = ne0 + sub;
                if (ne < E) { ns = src[ne]; ndn = dst[ne]; }
            }
        }

        // 3) transpose-reduce: 7 shuffles; lane sub holds dot of edge e0+sub
        bool hi4 = (sub & 4) != 0;
        float a0k = hi4 ? d[4] : d[0], a0s = hi4 ? d[0] : d[4];
        float a1k = hi4 ? d[5] : d[1], a1s = hi4 ? d[1] : d[5];
        float a2k = hi4 ? d[6] : d[2], a2s = hi4 ? d[2] : d[6];
        float a3k = hi4 ? d[7] : d[3], a3s = hi4 ? d[3] : d[7];
        a0k += __shfl_xor_sync(0xffffffffu, a0s, 4);
        a1k += __shfl_xor_sync(0xffffffffu, a1s, 4);
        a2k += __shfl_xor_sync(0xffffffffu, a2s, 4);
        a3k += __shfl_xor_sync(0xffffffffu, a3s, 4);
        bool hi2 = (sub & 2) != 0;
        float b0k = hi2 ? a2k : a0k, b0s = hi2 ? a0k : a2k;
        float b1k = hi2 ? a3k : a1k, b1s = hi2 ? a1k : a3k;
        b0k += __shfl_xor_sync(0xffffffffu, b0s, 2);
        b1k += __shfl_xor_sync(0xffffffffu, b1s, 2);
        bool hi1 = (sub & 1) != 0;
        float myd = hi1 ? b1k : b0k, cs = hi1 ? b0k : b1k;
        myd += __shfl_xor_sync(0xffffffffu, cs, 1);

        // 4) tail: lane sub handles edge e0+sub; indices already resolved, so
        //    the table gathers are the only memory dependency left.
        int e = e0 + sub;
        if (e < E) {
            float myr = __ldg(bondlength + e);   // L1 hit
            if (myr <= 4.0f) {
                float4 ps = *(const float4*)(g_srcTab + (size_t)s_ * 8);
                float  gs = g_srcTab[(size_t)s_ * 8 + 4];
                float4 pd = *(const float4*)(g_dstTab + (size_t)dn * 8);
                float  gd = g_dstTab[(size_t)dn * 8 + 4];

                float m  = gs + gd + myd + begv;
                float bo = 1.0f / (1.0f + __expf(-m));

                float p1 = __expf(ps.y + pd.y);
                float p3 = __expf(ps.w + pd.w);
                // p0*exp(-p1*r) == exp(a0 - p1*r); same for attract term
                float frep = __expf(ps.x + pd.x - p1 * myr);
                float fatt = __expf(ps.z + pd.z - p3 * myr);

                // cutoff: 1 for r<3.8; 0.5-0.5*sin(pi*(r-3.9)/0.2) in [3.8,4.0]
                float c = 1.0f;
                if (myr >= 3.8f)
                    c = 0.5f - 0.5f * __sinf(CUDART_PI_F * (myr - 3.9f) * 5.0f);

                float V = c * (frep - bo * fatt);
                atomicAdd(atom + dn, V);
                Vacc += V;
            }
        }

        // rotate prefetched indices into place for the next iteration
        s_ = ns; dn = ndn;
    }

    // once per block: energy accumulation
#pragma unroll
    for (int off = 16; off >= 1; off >>= 1)
        Vacc += __shfl_xor_sync(0xffffffffu, Vacc, off);
    if ((tid & 31) == 0 && Vacc != 0.0f)
        atomicAdd(&sEsum, Vacc);
    __syncthreads();
    if (tid == 0)
        atomicAdd(out0, sEsum * invN);
}

extern "C" void kernel_launch(void* const* d_in, const int* in_sizes, int n_in,
                              void* d_out, int out_size)
{
    const float* x    = (const float*)d_in[0];
    const float* x0   = (const float*)d_in[1];
    const float* y    = (const float*)d_in[2];
    const float* bond = (const float*)d_in[3];
    const int*   src  = (const int*)d_in[4];
    const int*   dst  = (const int*)d_in[5];
    const float* Wsg  = (const float*)d_in[6];
    const float* bsg  = (const float*)d_in[7];
    const float* Wdg  = (const float*)d_in[8];
    const float* bdg  = (const float*)d_in[9];
    const float* Weg  = (const float*)d_in[10];
    const float* beg  = (const float*)d_in[11];
    const float* Wsp  = (const float*)d_in[12];
    const float* bsp  = (const float*)d_in[13];
    const float* Wdp  = (const float*)d_in[14];

    const int N = in_sizes[0] / HID;   // 50000
    const int E = in_sizes[3];         // 1600000

    float* out = (float*)d_out;        // out[0] = energy, out[1..N] = atomwise

    // 1) per-node gate/param precompute + zero the output accumulators
    node_kernel<<<(N * 8 + 255) / 256, 256>>>(x, x0, Wsg, bsg, Wdg, bdg,
                                              Wsp, bsp, Wdp, out + 1, out, N);

    // 2) persistent edge kernel: R8 grid (148 x 5 = 740)
    int nChunks = (E + 255) / 256;
    int grid = 148 * 5;
    if (grid > nChunks) grid = nChunks;
    edge_kernel<<<grid, 256>>>(y, bond, src, dst, Weg, beg, out + 1, out,
                               E, 1.0f / (float)N);
}

// round 13
// speedup vs baseline: 1.5532x; 1.5532x over previous
#include <cuda_runtime.h>
#include <math_constants.h>

#define HID   64
#define MAXN  50000

// Per-node precomputed tables, stride 8 floats for float4 alignment.
// srcTab[n*8 + 0..3] = ps (x0·Wsp + bsp), [n*8+4] = gs (x·Wsg + bsg)
// dstTab[n*8 + 0..3] = pd (x0·Wdp),       [n*8+4] = gd (x·Wdg + bdg)
__device__ float g_srcTab[MAXN * 8];
__device__ float g_dstTab[MAXN * 8];

// 8 lanes per node; lane handles elements [sub*4 .. sub*4+3] and [32+sub*4 ..].
// Butterfly transpose-reduce; distributed stores. Also zeroes output accumulators.
__global__ void node_kernel(const float* __restrict__ x,
                            const float* __restrict__ x0,
                            const float* __restrict__ Wsg, const float* __restrict__ bsg,
                            const float* __restrict__ Wdg, const float* __restrict__ bdg,
                            const float* __restrict__ Wsp, const float* __restrict__ bsp,
                            const float* __restrict__ Wdp,
                            float* __restrict__ atom, float* __restrict__ out0,
                            int n)
{
    int t    = blockIdx.x * blockDim.x + threadIdx.x;
    int node = t >> 3;
    int sub  = t & 7;
    if (node >= n) return;

    const size_t base = (size_t)node * HID;
    const int h0 = sub * 4;        // first element of chunk A
    const int h1 = 32 + sub * 4;   // first element of chunk B

    float4 xa  = *(const float4*)(x  + base + h0);
    float4 xb  = *(const float4*)(x  + base + h1);
    float4 x0a = *(const float4*)(x0 + base + h0);
    float4 x0b = *(const float4*)(x0 + base + h1);

    float gs = 0.f, gd = 0.f;
    float v[8];                    // 0..3 = ps partials, 4..7 = pd partials
#pragma unroll
    for (int p = 0; p < 8; p++) v[p] = 0.f;

    const float* xav  = (const float*)&xa;
    const float* xbv  = (const float*)&xb;
    const float* x0av = (const float*)&x0a;
    const float* x0bv = (const float*)&x0b;

#pragma unroll
    for (int k = 0; k < 4; k++) {
        int ha = h0 + k, hb = h1 + k;
        gs += xav[k] * __ldg(Wsg + ha) + xbv[k] * __ldg(Wsg + hb);
        gd += xav[k] * __ldg(Wdg + ha) + xbv[k] * __ldg(Wdg + hb);
        float4 wsa = *(const float4*)(Wsp + ha * 4);
        float4 wsb = *(const float4*)(Wsp + hb * 4);
        float4 wda = *(const float4*)(Wdp + ha * 4);
        float4 wdb = *(const float4*)(Wdp + hb * 4);
        v[0] += x0av[k] * wsa.x + x0bv[k] * wsb.x;
        v[1] += x0av[k] * wsa.y + x0bv[k] * wsb.y;
        v[2] += x0av[k] * wsa.z + x0bv[k] * wsb.z;
        v[3] += x0av[k] * wsa.w + x0bv[k] * wsb.w;
        v[4] += x0av[k] * wda.x + x0bv[k] * wdb.x;
        v[5] += x0av[k] * wda.y + x0bv[k] * wdb.y;
        v[6] += x0av[k] * wda.z + x0bv[k] * wdb.z;
        v[7] += x0av[k] * wda.w + x0bv[k] * wdb.w;
    }

    // transpose-reduce: 7 shuffles; lane sub ends with sum over group of v[sub]
    bool hi4 = (sub & 4) != 0;
    float a0k = hi4 ? v[4] : v[0], a0s = hi4 ? v[0] : v[4];
    float a1k = hi4 ? v[5] : v[1], a1s = hi4 ? v[1] : v[5];
    float a2k = hi4 ? v[6] : v[2], a2s = hi4 ? v[2] : v[6];
    float a3k = hi4 ? v[7] : v[3], a3s = hi4 ? v[3] : v[7];
    a0k += __shfl_xor_sync(0xffffffffu, a0s, 4);
    a1k += __shfl_xor_sync(0xffffffffu, a1s, 4);
    a2k += __shfl_xor_sync(0xffffffffu, a2s, 4);
    a3k += __shfl_xor_sync(0xffffffffu, a3s, 4);
    bool hi2 = (sub & 2) != 0;
    float b0k = hi2 ? a2k : a0k, b0s = hi2 ? a0k : a2k;
    float b1k = hi2 ? a3k : a1k, b1s = hi2 ? a1k : a3k;
    b0k += __shfl_xor_sync(0xffffffffu, b0s, 2);
    b1k += __shfl_xor_sync(0xffffffffu, b1s, 2);
    bool hi1 = (sub & 1) != 0;
    float ck = hi1 ? b1k : b0k, cs = hi1 ? b0k : b1k;
    ck += __shfl_xor_sync(0xffffffffu, cs, 1);

    // plain reduce for the two gate scalars (6 shuffles)
#pragma unroll
    for (int off = 4; off >= 1; off >>= 1) {
        gs += __shfl_xor_sync(0xffffffffu, gs, off);
        gd += __shfl_xor_sync(0xffffffffu, gd, off);
    }

    // distributed stores: lane sub<4 -> srcTab param, sub>=4 -> dstTab param
    if (sub < 4)
        g_srcTab[(size_t)node * 8 + sub] = ck + __ldg(bsp + sub);
    else
        g_dstTab[(size_t)node * 8 + (sub - 4)] = ck;
    if (sub == 0) {
        g_srcTab[(size_t)node * 8 + 4] = gs + __ldg(bsg);
        g_dstTab[(size_t)node * 8 + 4] = gd + __ldg(bdg);
        atom[node] = 0.0f;                 // zero the scatter accumulator
        if (node == 0) *out0 = 0.0f;       // zero the energy accumulator
    }
}

// Persistent grid-stride edge kernel. Each block loops over chunks of 256
// edges (32 groups x 8 edges). Cross-iteration pipeline: the bond lengths
// for chunk i are loaded during iteration i-1, so the y loads of iteration i
// issue immediately — the serial bond->y DRAM chain is paid only once per
// block instead of once per wave. Tail is fully self-contained (no state
// carried across iterations besides the pure r[] prefetch — anything else
// defeats ptxas software pipelining; measured R9/R10/R12 regressions).
__global__ void __launch_bounds__(256, 5)
edge_kernel(const float* __restrict__ y,
            const float* __restrict__ bondlength,
            const int* __restrict__ src,
            const int* __restrict__ dst,
            const float* __restrict__ Weg,
            const float* __restrict__ beg,
            float* __restrict__ atom,
            float* __restrict__ out0,
            int E, float invN)
{
    __shared__ float sWeg[HID];
    __shared__ float sEsum;
    int tid = threadIdx.x;
    if (tid < HID) sWeg[tid] = Weg[tid];
    if (tid == 0)  sEsum = 0.0f;
    __syncthreads();

    const int sub      = tid & 7;
    const int grpInBlk = tid >> 3;             // 0..31
    const float4 wa = *(const float4*)(sWeg + sub * 4);
    const float4 wb = *(const float4*)(sWeg + 32 + sub * 4);
    const float begv = __ldg(beg);

    const int CHUNK = 256;                     // edges per block-iteration
    const int nChunks = (E + CHUNK - 1) / CHUNK;

    float Vacc = 0.0f;
    int chunk = blockIdx.x;

    float r[8];
    if (chunk < nChunks) {
        int e0 = chunk * CHUNK + grpInBlk * 8;
#pragma unroll
        for (int p = 0; p < 8; p++)
            r[p] = (e0 + p < E) ? __ldg(bondlength + e0 + p) : 5.0f;
    }

    for (; chunk < nChunks; chunk += gridDim.x) {
        const int e0 = chunk * CHUNK + grpInBlk * 8;
        const float* ybase = y + (size_t)e0 * HID;

        // 1) y loads gated on already-resident r[] (evict-first stream)
        float d[8];
#pragma unroll
        for (int p = 0; p < 8; p += 2) {
            float da = 0.f, db = 0.f;
            if (r[p] <= 4.0f) {
                const float* row = ybase + (size_t)p * HID;
                float4 a = __ldcs((const float4*)(row + sub * 4));
                float4 b = __ldcs((const float4*)(row + 32 + sub * 4));
                da = a.x*wa.x + a.y*wa.y + a.z*wa.z + a.w*wa.w
                   + b.x*wb.x + b.y*wb.y + b.z*wb.z + b.w*wb.w;
            }
            if (r[p + 1] <= 4.0f) {
                const float* row = ybase + (size_t)(p + 1) * HID;
                float4 a = __ldcs((const float4*)(row + sub * 4));
                float4 b = __ldcs((const float4*)(row + 32 + sub * 4));
                db = a.x*wa.x + a.y*wa.y + a.z*wa.z + a.w*wa.w
                   + b.x*wb.x + b.y*wb.y + b.z*wb.z + b.w*wb.w;
            }
            d[p] = da; d[p + 1] = db;
        }

        // 2) prefetch NEXT chunk's bond lengths straight into r[]
        {
            int nchunk = chunk + gridDim.x;
            if (nchunk < nChunks) {
                int ne0 = nchunk * CHUNK + grpInBlk * 8;
#pragma unroll
                for (int p = 0; p < 8; p++)
                    r[p] = (ne0 + p < E) ? __ldg(bondlength + ne0 + p) : 5.0f;
            }
        }

        // 3) transpose-reduce: 7 shuffles; lane sub holds dot of edge e0+sub
        bool hi4 = (sub & 4) != 0;
        float a0k = hi4 ? d[4] : d[0], a0s = hi4 ? d[0] : d[4];
        float a1k = hi4 ? d[5] : d[1], a1s = hi4 ? d[1] : d[5];
        float a2k = hi4 ? d[6] : d[2], a2s = hi4 ? d[2] : d[6];
        float a3k = hi4 ? d[7] : d[3], a3s = hi4 ? d[3] : d[7];
        a0k += __shfl_xor_sync(0xffffffffu, a0s, 4);
        a1k += __shfl_xor_sync(0xffffffffu, a1s, 4);
        a2k += __shfl_xor_sync(0xffffffffu, a2s, 4);
        a3k += __shfl_xor_sync(0xffffffffu, a3s, 4);
        bool hi2 = (sub & 2) != 0;
        float b0k = hi2 ? a2k : a0k, b0s = hi2 ? a0k : a2k;
        float b1k = hi2 ? a3k : a1k, b1s = hi2 ? a1k : a3k;
        b0k += __shfl_xor_sync(0xffffffffu, b0s, 2);
        b1k += __shfl_xor_sync(0xffffffffu, b1s, 2);
        bool hi1 = (sub & 1) != 0;
        float myd = hi1 ? b1k : b0k, cs = hi1 ? b0k : b1k;
        myd += __shfl_xor_sync(0xffffffffu, cs, 1);

        // 4) tail: lane sub handles edge e0+sub (bond reload = L1 hit)
        int e = e0 + sub;
        if (e < E) {
            float myr = __ldg(bondlength + e);
            if (myr <= 4.0f) {
                int s  = src[e];
                int dn = dst[e];
                float4 ps = *(const float4*)(g_srcTab + (size_t)s * 8);
                float  gs = g_srcTab[(size_t)s * 8 + 4];
                float4 pd = *(const float4*)(g_dstTab + (size_t)dn * 8);
                float  gd = g_dstTab[(size_t)dn * 8 + 4];

                float m  = gs + gd + myd + begv;
                float bo = 1.0f / (1.0f + __expf(-m));

                float p1 = __expf(ps.y + pd.y);
                float p3 = __expf(ps.w + pd.w);
                // p0*exp(-p1*r) == exp(a0 - p1*r); same for attract term
                float frep = __expf(ps.x + pd.x - p1 * myr);
                float fatt = __expf(ps.z + pd.z - p3 * myr);

                // cutoff: 1 for r<3.8; 0.5-0.5*sin(pi*(r-3.9)/0.2) in [3.8,4.0]
                float c = 1.0f;
                if (myr >= 3.8f)
                    c = 0.5f - 0.5f * __sinf(CUDART_PI_F * (myr - 3.9f) * 5.0f);

                float V = c * (frep - bo * fatt);
                atomicAdd(atom + dn, V);
                Vacc += V;
            }
        }
    }

    // once per block: energy accumulation
#pragma unroll
    for (int off = 16; off >= 1; off >>= 1)
        Vacc += __shfl_xor_sync(0xffffffffu, Vacc, off);
    if ((tid & 31) == 0 && Vacc != 0.0f)
        atomicAdd(&sEsum, Vacc);
    __syncthreads();
    if (tid == 0)
        atomicAdd(out0, sEsum * invN);
}

extern "C" void kernel_launch(void* const* d_in, const int* in_sizes, int n_in,
                              void* d_out, int out_size)
{
    const float* x    = (const float*)d_in[0];
    const float* x0   = (const float*)d_in[1];
    const float* y    = (const float*)d_in[2];
    const float* bond = (const float*)d_in[3];
    const int*   src  = (const int*)d_in[4];
    const int*   dst  = (const int*)d_in[5];
    const float* Wsg  = (const float*)d_in[6];
    const float* bsg  = (const float*)d_in[7];
    const float* Wdg  = (const float*)d_in[8];
    const float* bdg  = (const float*)d_in[9];
    const float* Weg  = (const float*)d_in[10];
    const float* beg  = (const float*)d_in[11];
    const float* Wsp  = (const float*)d_in[12];
    const float* bsp  = (const float*)d_in[13];
    const float* Wdp  = (const float*)d_in[14];

    const int N = in_sizes[0] / HID;   // 50000
    const int E = in_sizes[3];         // 1600000

    float* out = (float*)d_out;        // out[0] = energy, out[1..N] = atomwise

    // 1) per-node gate/param precompute + zero the output accumulators
    node_kernel<<<(N * 8 + 255) / 256, 256>>>(x, x0, Wsg, bsg, Wdg, bdg,
                                              Wsp, bsp, Wdp, out + 1, out, N);

    // 2) persistent fused edge kernel: 148 SMs x 5 blocks
    int nChunks = (E + 255) / 256;
    int grid = 148 * 5;
    if (grid > nChunks) grid = nChunks;
    edge_kernel<<<grid, 256>>>(y, bond, src, dst, Weg, beg, out + 1, out,
                               E, 1.0f / (float)N);
}